// round 13
// baseline (speedup 1.0000x reference)
#include <cuda_runtime.h>
#include <cuda_bf16.h>
#include <cstdint>

// ---------------------------------------------------------------------------
// Compile-time normalization constants K(l,m) baked in as immediates:
//   K = sqrt((2l+1)/(4pi) * (l-m)!/(l+m)!),   times sqrt(2) for m != 0
// ---------------------------------------------------------------------------
namespace {

constexpr double csqrt(double x) {
    double g = x > 1.0 ? x : 1.0;
    for (int i = 0; i < 100; i++) g = 0.5 * (g + x / g);
    return g;
}
constexpr double dfact(int n) {
    double r = 1.0;
    for (int i = 2; i <= n; i++) r *= (double)i;
    return r;
}
constexpr double PI_D = 3.14159265358979323846;

struct KTab { float c[8][8]; };

constexpr KTab mk_ktab() {
    KTab t{};
    for (int l = 0; l < 8; l++)
        for (int m = 0; m <= l; m++) {
            double K = csqrt((2.0 * l + 1.0) / (4.0 * PI_D)
                             * dfact(l - m) / dfact(l + m));
            if (m > 0) K *= csqrt(2.0);
            t.c[l][m] = (float)K;
        }
    return t;
}

__device__ constexpr KTab g_Kc = mk_ktab();

} // namespace

// ---------------------------------------------------------------------------
// PERSISTENT l-outer pipeline, 2-slot SMEM ring, cross-tile input prefetch.
// grid = 148*6 blocks; each block loops over tiles of 256 points. At the top
// of tile k's body the inputs for tile k+gridDim are LDG-issued (consumed
// ~2000 cycles later), hiding DRAM latency on every tile but the first.
// Region staging in output order (lane stride w odd => conflict-free STS);
// thread 0 issues one cp.async.bulk (3..15 KB) per region. Ring slot =
// running region counter & 1; wait_group 1 before reuse.
// NON-FULL tiles first drain ALL outstanding bulk copies (wait_group 0 +
// barrier) before staging: their manual-copy path has no wait_group, and
// without the drain they could overwrite a slot the TMA engine is still
// reading from the previous full tile (this corrupted l=7 in R12).
// l = 0 is the constant Y00 (direct store).
// ---------------------------------------------------------------------------
constexpr int TPB = 256;
constexpr int SLOT_FLOATS = 15 * TPB;            // largest region (l=7)

__device__ __forceinline__ uint32_t smem_u32(const void* p) {
    uint32_t a;
    asm("{ .reg .u64 t; cvta.to.shared.u64 t, %1; cvt.u32.u64 %0, t; }"
        : "=r"(a) : "l"(p));
    return a;
}

__global__ __launch_bounds__(TPB, 6)
void sph_harm_kernel(const float* __restrict__ cos_theta,
                     const float* __restrict__ phi,
                     float* __restrict__ out,
                     int N, int tiles)
{
    __shared__ float slot[2][SLOT_FLOATS];       // 30720 B

    const int t = threadIdx.x;
    int rc = 0;                                  // global region ring counter

    // ---- prologue: load inputs for first tile ----
    int tile = blockIdx.x;
    float x, p;
    {
        const int n0 = tile * TPB + t;
        const int nc = (tile < tiles) ? ((n0 < N) ? n0 : (N - 1)) : 0;
        x = cos_theta[nc];
        p = phi[nc];
    }

    for (; tile < tiles; tile += gridDim.x) {
        // ---- prefetch inputs for the NEXT tile this block will run ----
        const int ntile = tile + gridDim.x;
        float xn = 0.0f, pn = 0.0f;
        if (ntile < tiles) {
            const int nn = ntile * TPB + t;
            const int nc = (nn < N) ? nn : (N - 1);
            xn = __ldg(cos_theta + nc);          // issued here, used at end
            pn = __ldg(phi + nc);
        }

        const long long bs = (long long)tile * TPB;
        const int n    = (int)bs + t;
        const int rows = (int)min((long long)TPB, (long long)N - bs);
        const bool full = (rows == TPB) && ((N & 3) == 0);

        if (!full) {
            // Drain ALL in-flight bulk copies before this tile stages into
            // the ring: the fallback path below has no wait_group, and a
            // prior tile's copy may still be reading a slot.
            if (t == 0)
                asm volatile("cp.async.bulk.wait_group 0;" ::: "memory");
            __syncthreads();
        }

        const float s = sqrtf(fmaxf(1.0f - x * x, 0.0f));
        float sp, cp;
        __sincosf(p, &sp, &cp);

        // l = 0 : Y00 is a constant.
        if (n < N) out[n] = g_Kc.c[0][0];

        // Recurrence state (fully unrolled -> registers).
        float Pp[8];    // P_{l-1}^m
        float Ppp[8];   // P_{l-2}^m
        float cmv[8], smv[8];
        Pp[0] = 1.0f;
        cmv[0] = 1.0f; smv[0] = 0.0f;

        #pragma unroll
        for (int l = 1; l <= 7; l++) {
            float Pl[8];
            #pragma unroll
            for (int m = 0; m <= l - 2; m++)
                Pl[m] = ((2.0f * l - 1.0f) * x * Pp[m]
                         - (float)(l + m - 1) * Ppp[m])
                        * (1.0f / (float)(l - m));
            Pl[l - 1] = (2.0f * l - 1.0f) * x * Pp[l - 1];
            Pl[l]     = -(2.0f * l - 1.0f) * s * Pp[l - 1]; // Condon-Shortley

            cmv[l] = cp * cmv[l - 1] - sp * smv[l - 1];
            smv[l] = sp * cmv[l - 1] + cp * smv[l - 1];

            const int w = 2 * l + 1;
            float* buf = slot[rc & 1];

            // stage region l (lane stride w odd -> conflict-free)
            {
                const int base = t * w;
                buf[base + l] = g_Kc.c[l][0] * Pl[0];
                #pragma unroll
                for (int m = 1; m <= l; m++) {
                    const float kp = g_Kc.c[l][m] * Pl[m];
                    buf[base + (l - m)] = kp * smv[m];
                    buf[base + (l + m)] = kp * cmv[m];
                }
            }

            __syncthreads();                     // region staged

            if (full) {
                if (t == 0) {
                    asm volatile("fence.proxy.async.shared::cta;" ::: "memory");
                    const uint32_t src = smem_u32(buf);
                    float* dstp = out + (size_t)N * (size_t)(l * l)
                                      + (size_t)bs * (size_t)w;
                    const uint32_t bytes = (uint32_t)(TPB * w * 4);
                    asm volatile(
                        "cp.async.bulk.global.shared::cta.bulk_group "
                        "[%0], [%1], %2;"
                        :: "l"(dstp), "r"(src), "r"(bytes) : "memory");
                    asm volatile("cp.async.bulk.commit_group;" ::: "memory");
                    // <=1 outstanding: copy for rc-2 (this slot's previous
                    // occupant) has drained before the slot is re-staged.
                    asm volatile("cp.async.bulk.wait_group 1;" ::: "memory");
                }
            } else {
                // tail tile fallback (one tile at N = 2M)
                float* dst = out + (size_t)N * (size_t)(l * l)
                                 + (size_t)bs * (size_t)w;
                const int cnt = rows * w;
                for (int i = t; i < cnt; i += TPB)
                    dst[i] = buf[i];
            }

            __syncthreads();                     // slot-reuse safety
            rc++;

            #pragma unroll
            for (int m = 0; m <= l - 1; m++) Ppp[m] = Pp[m];
            #pragma unroll
            for (int m = 0; m <= l; m++)     Pp[m]  = Pl[m];
        }

        // rotate prefetched inputs into place
        x = xn; p = pn;
    }

    if (t == 0)
        asm volatile("cp.async.bulk.wait_group 0;" ::: "memory");
}

extern "C" void kernel_launch(void* const* d_in, const int* in_sizes, int n_in,
                              void* d_out, int out_size)
{
    const float* cos_theta = (const float*)d_in[0];
    const float* phi       = (const float*)d_in[1];
    float* out             = (float*)d_out;
    const int N = in_sizes[0];

    const int tiles = (N + TPB - 1) / TPB;
    int grid = 148 * 6;                          // persistent: 6 blocks/SM
    if (grid > tiles) grid = tiles;

    sph_harm_kernel<<<grid, TPB>>>(cos_theta, phi, out, N, tiles);
}

// round 14
// speedup vs baseline: 1.1408x; 1.1408x over previous
#include <cuda_runtime.h>
#include <cuda_bf16.h>
#include <cstdint>

// ---------------------------------------------------------------------------
// Compile-time normalization constants K(l,m) baked in as immediates:
//   K = sqrt((2l+1)/(4pi) * (l-m)!/(l+m)!),   times sqrt(2) for m != 0
// ---------------------------------------------------------------------------
namespace {

constexpr double csqrt(double x) {
    double g = x > 1.0 ? x : 1.0;
    for (int i = 0; i < 100; i++) g = 0.5 * (g + x / g);
    return g;
}
constexpr double dfact(int n) {
    double r = 1.0;
    for (int i = 2; i <= n; i++) r *= (double)i;
    return r;
}
constexpr double PI_D = 3.14159265358979323846;

struct KTab { float c[8][8]; };

constexpr KTab mk_ktab() {
    KTab t{};
    for (int l = 0; l < 8; l++)
        for (int m = 0; m <= l; m++) {
            double K = csqrt((2.0 * l + 1.0) / (4.0 * PI_D)
                             * dfact(l - m) / dfact(l + m));
            if (m > 0) K *= csqrt(2.0);
            t.c[l][m] = (float)K;
        }
    return t;
}

__device__ constexpr KTab g_Kc = mk_ktab();

} // namespace

// ---------------------------------------------------------------------------
// R8 structure (best known: 80.4us) + drain-hiding epilogue.
// One block = 256 points. 2-slot SMEM ring (15 KB slots, 30.7 KB total,
// 6 blocks/SM). Regions l=1..6: staged in slot (l&1) in output order (lane
// stride w odd => conflict-free STS), thread 0 issues cp.async.bulk
// (1.5..13 KB) + wait_group 1 (slot reused at l+2 has drained).
// Region l=7 (15 KB, the largest): staged, then copied MANUALLY with
// LDS.128/STG.128 by all threads — this overlaps the drain of the l=6 bulk
// copy, so the final wait_group 0 is ~free (no dead drain tail per block).
// Slot safety for l=7: wait_group 1 at l=6's issue guarantees l=5's copy
// (same slot as l=7) completed. l = 0 is the constant Y00 (direct store).
// ---------------------------------------------------------------------------
constexpr int TPB = 256;
constexpr int SLOT_FLOATS = 15 * TPB;          // sized for the largest region

__device__ __forceinline__ uint32_t smem_u32(const void* p) {
    uint32_t a;
    asm("{ .reg .u64 t; cvta.to.shared.u64 t, %1; cvt.u32.u64 %0, t; }"
        : "=r"(a) : "l"(p));
    return a;
}

__global__ __launch_bounds__(TPB, 6)
void sph_harm_kernel(const float* __restrict__ cos_theta,
                     const float* __restrict__ phi,
                     float* __restrict__ out,
                     int N)
{
    __shared__ float slot[2][SLOT_FLOATS];     // 30720 B

    const int t  = threadIdx.x;
    const long long bs = (long long)blockIdx.x * TPB;
    const int n    = (int)bs + t;
    const int rows = (int)min((long long)TPB, (long long)N - bs);
    const bool full = (rows == TPB) && ((N & 3) == 0);

    const int nc = (n < N) ? n : (N - 1);

    const float x = cos_theta[nc];
    const float p = phi[nc];
    const float s = sqrtf(fmaxf(1.0f - x * x, 0.0f));

    float sp, cp;
    __sincosf(p, &sp, &cp);

    // l = 0 : Y00 is a constant.
    if (n < N) out[n] = g_Kc.c[0][0];

    // Recurrence state (fully unrolled -> registers).
    float Pp[8];    // P_{l-1}^m
    float Ppp[8];   // P_{l-2}^m
    float cmv[8], smv[8];
    Pp[0] = 1.0f;
    cmv[0] = 1.0f; smv[0] = 0.0f;

    #pragma unroll
    for (int l = 1; l <= 7; l++) {
        float Pl[8];
        #pragma unroll
        for (int m = 0; m <= l - 2; m++)
            Pl[m] = ((2.0f * l - 1.0f) * x * Pp[m]
                     - (float)(l + m - 1) * Ppp[m]) * (1.0f / (float)(l - m));
        Pl[l - 1] = (2.0f * l - 1.0f) * x * Pp[l - 1];
        Pl[l]     = -(2.0f * l - 1.0f) * s * Pp[l - 1];   // Condon-Shortley

        cmv[l] = cp * cmv[l - 1] - sp * smv[l - 1];
        smv[l] = sp * cmv[l - 1] + cp * smv[l - 1];

        const int w = 2 * l + 1;
        float* buf = slot[l & 1];

        // stage region l (lane stride w odd -> conflict-free)
        {
            const int base = t * w;
            buf[base + l] = g_Kc.c[l][0] * Pl[0];
            #pragma unroll
            for (int m = 1; m <= l; m++) {
                const float kp = g_Kc.c[l][m] * Pl[m];
                buf[base + (l - m)] = kp * smv[m];
                buf[base + (l + m)] = kp * cmv[m];
            }
        }

        __syncthreads();                       // region staged

        if (l <= 6) {
            if (full) {
                if (t == 0) {
                    asm volatile("fence.proxy.async.shared::cta;" ::: "memory");
                    const uint32_t src = smem_u32(buf);
                    float* dstp = out + (size_t)N * (size_t)(l * l)
                                      + (size_t)bs * (size_t)w;
                    const uint32_t bytes = (uint32_t)(TPB * w * 4);
                    asm volatile(
                        "cp.async.bulk.global.shared::cta.bulk_group "
                        "[%0], [%1], %2;"
                        :: "l"(dstp), "r"(src), "r"(bytes) : "memory");
                    asm volatile("cp.async.bulk.commit_group;" ::: "memory");
                    // <=1 outstanding: copy issued 2 regions ago (the slot
                    // about to be re-staged) has drained.
                    asm volatile("cp.async.bulk.wait_group 1;" ::: "memory");
                }
            } else {
                // tail block fallback (one block at N = 2M)
                float* dst = out + (size_t)N * (size_t)(l * l)
                                 + (size_t)bs * (size_t)w;
                const int cnt = rows * w;
                for (int i = t; i < cnt; i += TPB)
                    dst[i] = buf[i];
            }
            __syncthreads();                   // slot-reuse safety
        } else {
            // ---- l = 7 epilogue: manual copy overlapping the TMA drain ----
            if (full) {
                const float4* src = (const float4*)buf;
                float4* dst = (float4*)(out + (size_t)N * 49u
                                            + (size_t)bs * 15u);
                constexpr int cnt4 = (TPB * 15) / 4;   // 960
                #pragma unroll
                for (int i = t; i < cnt4; i += TPB)
                    dst[i] = src[i];
                if (t == 0)   // l=6 copy has had ~15 KB of STG time to drain
                    asm volatile("cp.async.bulk.wait_group 0;" ::: "memory");
            } else {
                float* dst = out + (size_t)N * 49u + (size_t)bs * 15u;
                const int cnt = rows * 15;
                for (int i = t; i < cnt; i += TPB)
                    dst[i] = buf[i];
            }
        }

        #pragma unroll
        for (int m = 0; m <= l - 1; m++) Ppp[m] = Pp[m];
        #pragma unroll
        for (int m = 0; m <= l; m++)     Pp[m]  = Pl[m];
    }
}

extern "C" void kernel_launch(void* const* d_in, const int* in_sizes, int n_in,
                              void* d_out, int out_size)
{
    const float* cos_theta = (const float*)d_in[0];
    const float* phi       = (const float*)d_in[1];
    float* out             = (float*)d_out;
    const int N = in_sizes[0];

    const int blocks = (N + TPB - 1) / TPB;
    sph_harm_kernel<<<blocks, TPB>>>(cos_theta, phi, out, N);
}